// round 8
// baseline (speedup 1.0000x reference)
#include <cuda_runtime.h>
#include <cuda_bf16.h>

#define BB 64
#define SS 512
#define HH 1024
#define TT 17

// ---------------------------------------------------------------------------
// GEMM: feats[r][t] = sum_h x[r][h]*W[t][h] + b[t]  (M=32768, K=1024, N=17)
// 64 threads / 128 rows per block: each thread owns TWO rows, so every
// broadcast W LDS feeds 4 FFMA2 (was 2). Static smem 39.4 KB (no opt-in),
// ~5 CTAs/SM. Accumulation in packed fma.rn.f32x2 (even/odd-k partials).
// ---------------------------------------------------------------------------
#define GEMM_THREADS 64
#define ROWS_PB      128
#define KTILE        64
#define XS_STRIDE    68
#define WT_STRIDE    68

typedef unsigned long long u64;

__device__ __forceinline__ u64 fma2(u64 a, u64 b, u64 c) {
    u64 d;
    asm("fma.rn.f32x2 %0, %1, %2, %3;" : "=l"(d) : "l"(a), "l"(b), "l"(c));
    return d;
}

__global__ __launch_bounds__(GEMM_THREADS) void gemm_feats(
    const float* __restrict__ x, const float* __restrict__ W,
    const float* __restrict__ bias, float* __restrict__ feats)
{
    __shared__ float xs[ROWS_PB * XS_STRIDE];   // 34816 B
    __shared__ float wt[TT * WT_STRIDE];        //  4624 B

    const int tid  = threadIdx.x;
    const int row0 = blockIdx.x * ROWS_PB;

    u64 accA[TT], accB[TT];
#pragma unroll
    for (int t = 0; t < TT; t++) { accA[t] = 0ull; accB[t] = 0ull; }

    for (int kt = 0; kt < HH / KTILE; kt++) {
        // Stage x tile [128 rows x 64 k]: 2048 float4, 32 per thread, coalesced
#pragma unroll
        for (int p = 0; p < 32; p++) {
            int idx = tid + p * GEMM_THREADS;
            int r = idx >> 4;
            int c = idx & 15;
            float4 v = *(const float4*)(x + (size_t)(row0 + r) * HH + kt * KTILE + c * 4);
            *(float4*)&xs[r * XS_STRIDE + c * 4] = v;
        }
        // Stage W slab [17 x 64]: 272 float4
        for (int idx = tid; idx < TT * 16; idx += GEMM_THREADS) {
            int t = idx >> 4;
            int c = idx & 15;
            float4 v = *(const float4*)(W + (size_t)t * HH + kt * KTILE + c * 4);
            *(float4*)&wt[t * WT_STRIDE + c * 4] = v;
        }
        __syncthreads();

#pragma unroll
        for (int c = 0; c < 16; c++) {
            ulonglong2 xa = *(const ulonglong2*)&xs[tid * XS_STRIDE + c * 4];
            ulonglong2 xb = *(const ulonglong2*)&xs[(tid + 64) * XS_STRIDE + c * 4];
#pragma unroll
            for (int t = 0; t < TT; t++) {
                ulonglong2 wv = *(const ulonglong2*)&wt[t * WT_STRIDE + c * 4];
                accA[t] = fma2(xa.x, wv.x, accA[t]);
                accA[t] = fma2(xa.y, wv.y, accA[t]);
                accB[t] = fma2(xb.x, wv.x, accB[t]);
                accB[t] = fma2(xb.y, wv.y, accB[t]);
            }
        }
        __syncthreads();
    }

    float* oa = feats + (size_t)(row0 + tid) * TT;
    float* ob = feats + (size_t)(row0 + tid + 64) * TT;
#pragma unroll
    for (int t = 0; t < TT; t++) {
        float2 pa = *(float2*)&accA[t];
        float2 pb = *(float2*)&accB[t];
        float bs = bias[t];
        oa[t] = pa.x + pa.y + bs;
        ob[t] = pb.x + pb.y + bs;
    }
}

// ---------------------------------------------------------------------------
// Viterbi: one block per batch. 4 warps fill feats smem; warp 0 runs the scan.
// Score broadcast via double-buffered smem vector (STS + syncwarp + 5
// broadcast LDS) instead of 17 SHFLs (slow MIO path). Argmax = FMNMX value
// tree + parallel-equality + IMNMX min-tree (first-occurrence == jnp.argmax).
// ---------------------------------------------------------------------------
__global__ __launch_bounds__(128) void viterbi_kernel(
    const float* __restrict__ feats, const float* __restrict__ trans,
    const float* __restrict__ start_trans, const float* __restrict__ end_trans,
    const int* __restrict__ nwords, float* __restrict__ out_tags)
{
    __shared__ float fs[SS * TT];                  // 34816 B
    __shared__ unsigned char bp[SS * TT];          //  8704 B
    __shared__ __align__(16) float sc[2][20];      // double-buffered score vec

    const int b   = blockIdx.x;
    const int tid = threadIdx.x;
    const int nw  = nwords[b];

    // Cooperative feats fill (only rows < nw are ever read)
    const float4* fb4 = (const float4*)(feats + (size_t)b * SS * TT);
    const int n4 = (nw * TT + 3) >> 2;
    for (int i = tid; i < n4; i += 128)
        ((float4*)fs)[i] = fb4[i];
    __syncthreads();

    if (tid >= 32) return;   // warps 1-3 done

    const int jj = (tid < TT) ? tid : (TT - 1);
    float tcol[TT];
#pragma unroll
    for (int i = 0; i < TT; i++) tcol[i] = trans[i * TT + jj];

    float score = start_trans[jj] + fs[jj];        // t = 0 (always unmasked)
    if (tid < TT) sc[1][jj] = score;               // buffer (t=1)&1 == 1
    __syncwarp();

    for (int t = 1; t < nw; t++) {
        const float* s = sc[t & 1];
        const float f  = fs[t * TT + jj];          // independent LDS

        float4 s0 = *(const float4*)(s);
        float4 s1 = *(const float4*)(s + 4);
        float4 s2 = *(const float4*)(s + 8);
        float4 s3 = *(const float4*)(s + 12);
        float  sg = s[16];

        float c[TT];
        c[0]  = s0.x + tcol[0];  c[1]  = s0.y + tcol[1];
        c[2]  = s0.z + tcol[2];  c[3]  = s0.w + tcol[3];
        c[4]  = s1.x + tcol[4];  c[5]  = s1.y + tcol[5];
        c[6]  = s1.z + tcol[6];  c[7]  = s1.w + tcol[7];
        c[8]  = s2.x + tcol[8];  c[9]  = s2.y + tcol[9];
        c[10] = s2.z + tcol[10]; c[11] = s2.w + tcol[11];
        c[12] = s3.x + tcol[12]; c[13] = s3.y + tcol[13];
        c[14] = s3.z + tcol[14]; c[15] = s3.w + tcol[15];
        c[16] = sg   + tcol[16];

        // max value: FMNMX tree, depth 5
        float m8[8];
#pragma unroll
        for (int p = 0; p < 8; p++) m8[p] = fmaxf(c[2 * p], c[2 * p + 1]);
        float m4[4];
#pragma unroll
        for (int p = 0; p < 4; p++) m4[p] = fmaxf(m8[2 * p], m8[2 * p + 1]);
        float bv = fmaxf(fmaxf(fmaxf(m4[0], m4[1]), fmaxf(m4[2], m4[3])), c[16]);

        score = bv + f;
        if (tid < TT) sc[(t + 1) & 1][jj] = score;   // publish for next step
        __syncwarp();

        // first index equal to bv (off the serial chain)
        int e[TT];
#pragma unroll
        for (int i = 0; i < TT; i++) e[i] = (c[i] == bv) ? i : 31;
        int i8[8];
#pragma unroll
        for (int p = 0; p < 8; p++) i8[p] = min(e[2 * p], e[2 * p + 1]);
        int i4[4];
#pragma unroll
        for (int p = 0; p < 4; p++) i4[p] = min(i8[2 * p], i8[2 * p + 1]);
        int bi = min(min(min(i4[0], i4[1]), min(i4[2], i4[3])), e[16]);

        if (tid < TT) bp[t * TT + jj] = (unsigned char)bi;
    }

    __syncwarp();   // bp + final score vector visible to lane 0

    if (tid == 0) {
        const float* s = sc[nw & 1];
        int cur = 0;
        float bv = s[0] + end_trans[0];
#pragma unroll
        for (int i = 1; i < TT; i++) {
            float v = s[i] + end_trans[i];
            if (v > bv) { bv = v; cur = i; }
        }

        float* o = out_tags + (size_t)b * SS;
        int t = SS - 1;
        for (; t >= nw; t--) o[t] = 0.0f;          // masked region
        for (; t >= 1; t--) {
            o[t] = (float)cur;
            cur = bp[t * TT + cur];
        }
        o[0] = (float)cur;                          // nwords >= 1
    }
}

// ---------------------------------------------------------------------------
// Inputs: x, W, b, transitions, start_trans, end_trans, nwords
// Output: [padded_tags (B*S) | feats (B*S*T)] float32
// ---------------------------------------------------------------------------
extern "C" void kernel_launch(void* const* d_in, const int* in_sizes, int n_in,
                              void* d_out, int out_size)
{
    const float* x     = (const float*)d_in[0];
    const float* W     = (const float*)d_in[1];
    const float* bias  = (const float*)d_in[2];
    const float* trans = (const float*)d_in[3];
    const float* st    = (const float*)d_in[4];
    const float* en    = (const float*)d_in[5];
    const int*   nw    = (const int*)d_in[6];

    float* out   = (float*)d_out;
    float* tags  = out;                // B*S
    float* feats = out + BB * SS;      // B*S*T

    gemm_feats<<<(BB * SS) / ROWS_PB, GEMM_THREADS>>>(x, W, bias, feats);
    viterbi_kernel<<<BB, 128>>>(feats, trans, st, en, nw, tags);
}

// round 11
// speedup vs baseline: 1.2274x; 1.2274x over previous
#include <cuda_runtime.h>
#include <cuda_bf16.h>

#define BB 64
#define SS 512
#define HH 1024
#define TT 17

typedef unsigned long long u64;

__device__ __forceinline__ u64 fma2(u64 a, u64 b, u64 c) {
    u64 d;
    asm("fma.rn.f32x2 %0, %1, %2, %3;" : "=l"(d) : "l"(a), "l"(b), "l"(c));
    return d;
}
__device__ __forceinline__ u64 add2(u64 a, u64 b) {
    u64 d;
    asm("add.rn.f32x2 %0, %1, %2;" : "=l"(d) : "l"(a), "l"(b));
    return d;
}
__device__ __forceinline__ u64 pack2(float lo, float hi) {
    u64 d;
    asm("mov.b64 %0, {%1, %2};" : "=l"(d) : "f"(lo), "f"(hi));
    return d;
}

// ---------------------------------------------------------------------------
// GEMM: feats[r][t] = sum_h x[r][h]*W[t][h] + b[t]  (M=32768, K=1024, N=17)
// 128 threads / 64 rows per block, tags split 2-way across thread halves
// (g=0: tags 0..8, g=1: tags 9..16). Grid 512 => 2048 warps => latency hidden.
// k-packed fma.rn.f32x2 accumulation; W slab + x tile staged in static smem.
// ---------------------------------------------------------------------------
#define GEMM_THREADS 128
#define ROWS_PB      64
#define KTILE        64
#define XS_STRIDE    68
#define WT_STRIDE    68

template<int T0, int CNT>
__device__ __forceinline__ void acc_tile(const float* __restrict__ xs_row,
                                         const float* __restrict__ wt, u64* acc)
{
#pragma unroll
    for (int c = 0; c < 16; c++) {
        ulonglong2 xv = *(const ulonglong2*)(xs_row + c * 4);
#pragma unroll
        for (int u = 0; u < CNT; u++) {
            ulonglong2 wv = *(const ulonglong2*)(wt + (T0 + u) * WT_STRIDE + c * 4);
            acc[u] = fma2(xv.x, wv.x, acc[u]);
            acc[u] = fma2(xv.y, wv.y, acc[u]);
        }
    }
}

__global__ __launch_bounds__(GEMM_THREADS) void gemm_feats(
    const float* __restrict__ x, const float* __restrict__ W,
    const float* __restrict__ bias, float* __restrict__ feats)
{
    __shared__ float xs[ROWS_PB * XS_STRIDE];   // 17408 B
    __shared__ float wt[TT * WT_STRIDE];        //  4624 B

    const int tid  = threadIdx.x;
    const int r    = tid & 63;         // row within tile
    const int g    = tid >> 6;         // tag group: 0 -> [0,9), 1 -> [9,17)
    const int row0 = blockIdx.x * ROWS_PB;

    u64 acc[9];
#pragma unroll
    for (int u = 0; u < 9; u++) acc[u] = 0ull;

    for (int kt = 0; kt < HH / KTILE; kt++) {
        // Stage x tile [64 rows x 64 k]: 1024 float4, 8 per thread, coalesced
#pragma unroll
        for (int p = 0; p < 8; p++) {
            int idx = tid + p * GEMM_THREADS;
            int rr = idx >> 4;
            int cc = idx & 15;
            float4 v = *(const float4*)(x + (size_t)(row0 + rr) * HH + kt * KTILE + cc * 4);
            *(float4*)&xs[rr * XS_STRIDE + cc * 4] = v;
        }
        // Stage W slab [17 x 64]: 272 float4
        for (int idx = tid; idx < TT * 16; idx += GEMM_THREADS) {
            int t = idx >> 4;
            int cc = idx & 15;
            float4 v = *(const float4*)(W + (size_t)t * HH + kt * KTILE + cc * 4);
            *(float4*)&wt[t * WT_STRIDE + cc * 4] = v;
        }
        __syncthreads();

        const float* xs_row = &xs[r * XS_STRIDE];
        if (g == 0) acc_tile<0, 9>(xs_row, wt, acc);
        else        acc_tile<9, 8>(xs_row, wt, acc);
        __syncthreads();
    }

    float* o = feats + (size_t)(row0 + r) * TT;
    if (g == 0) {
#pragma unroll
        for (int u = 0; u < 9; u++) {
            float2 p = *(float2*)&acc[u];
            o[u] = p.x + p.y + bias[u];
        }
    } else {
#pragma unroll
        for (int u = 0; u < 8; u++) {
            float2 p = *(float2*)&acc[u];
            o[9 + u] = p.x + p.y + bias[9 + u];
        }
    }
}

// ---------------------------------------------------------------------------
// Viterbi: one block per batch. 4 warps fill feats smem; warp 0 runs the scan.
// Score exchange via double-buffered smem vector. Candidate adds in packed
// f32x2 (score pairs come packed free from LDS.128); max tree in scalar FMNMX
// on the aliased halves (unpack = register naming, 0 instrs). Argmax index
// via parallel equality + IMNMX min-tree (first-occurrence == jnp.argmax),
// off the serial dependency chain.
// ---------------------------------------------------------------------------
__global__ __launch_bounds__(128) void viterbi_kernel(
    const float* __restrict__ feats, const float* __restrict__ trans,
    const float* __restrict__ start_trans, const float* __restrict__ end_trans,
    const int* __restrict__ nwords, float* __restrict__ out_tags)
{
    __shared__ float fs[SS * TT];                  // 34816 B
    __shared__ unsigned char bp[SS * TT];          //  8704 B
    __shared__ __align__(16) float sc[2][20];      // double-buffered score vec

    const int b   = blockIdx.x;
    const int tid = threadIdx.x;
    const int nw  = nwords[b];

    // Cooperative feats fill (only rows < nw are read)
    const float4* fb4 = (const float4*)(feats + (size_t)b * SS * TT);
    const int n4 = (nw * TT + 3) >> 2;
    for (int i = tid; i < n4; i += 128)
        ((float4*)fs)[i] = fb4[i];
    __syncthreads();

    if (tid >= 32) return;   // warps 1-3 done

    const int jj = (tid < TT) ? tid : (TT - 1);

    // transition column for my tag, packed over source pairs
    float tcol[TT];
#pragma unroll
    for (int i = 0; i < TT; i++) tcol[i] = trans[i * TT + jj];
    u64 tc2[8];
#pragma unroll
    for (int p = 0; p < 8; p++) tc2[p] = pack2(tcol[2 * p], tcol[2 * p + 1]);
    const float tc16 = tcol[16];

    float score = start_trans[jj] + fs[jj];        // t = 0 (always unmasked)
    if (tid < TT) sc[1][jj] = score;               // buffer (t=1)&1 == 1
    __syncwarp();

    for (int t = 1; t < nw; t++) {
        const float* s = sc[t & 1];
        const float f  = fs[t * TT + jj];          // independent LDS

        // score pairs straight from vector loads
        ulonglong2 sA = *(const ulonglong2*)(s);       // pairs (0,1) (2,3)
        ulonglong2 sB = *(const ulonglong2*)(s + 4);   // pairs (4,5) (6,7)
        ulonglong2 sC = *(const ulonglong2*)(s + 8);   // pairs (8,9) (10,11)
        ulonglong2 sD = *(const ulonglong2*)(s + 12);  // pairs (12,13)(14,15)
        float s16 = s[16];

        u64 c2[8];
        c2[0] = add2(sA.x, tc2[0]); c2[1] = add2(sA.y, tc2[1]);
        c2[2] = add2(sB.x, tc2[2]); c2[3] = add2(sB.y, tc2[3]);
        c2[4] = add2(sC.x, tc2[4]); c2[5] = add2(sC.y, tc2[5]);
        c2[6] = add2(sD.x, tc2[6]); c2[7] = add2(sD.y, tc2[7]);
        float c16 = s16 + tc16;

        // unpack = register aliasing (free)
        float c[16];
#pragma unroll
        for (int p = 0; p < 8; p++) {
            float2 cp = *(float2*)&c2[p];
            c[2 * p] = cp.x; c[2 * p + 1] = cp.y;
        }

        // scalar FMNMX max tree, depth 5
        float m8[8];
#pragma unroll
        for (int p = 0; p < 8; p++) m8[p] = fmaxf(c[2 * p], c[2 * p + 1]);
        float m4[4];
#pragma unroll
        for (int p = 0; p < 4; p++) m4[p] = fmaxf(m8[2 * p], m8[2 * p + 1]);
        float bv = fmaxf(fmaxf(fmaxf(m4[0], m4[1]), fmaxf(m4[2], m4[3])), c16);

        score = bv + f;
        if (tid < TT) sc[(t + 1) & 1][jj] = score;   // publish for next step
        __syncwarp();

        // index: first i with c[i] == bv (off the serial chain)
        int e[16];
#pragma unroll
        for (int i = 0; i < 16; i++) e[i] = (c[i] == bv) ? i : 31;
        int e16 = (c16 == bv) ? 16 : 31;
        int i8[8];
#pragma unroll
        for (int p = 0; p < 8; p++) i8[p] = min(e[2 * p], e[2 * p + 1]);
        int i4[4];
#pragma unroll
        for (int p = 0; p < 4; p++) i4[p] = min(i8[2 * p], i8[2 * p + 1]);
        int bi = min(min(min(i4[0], i4[1]), min(i4[2], i4[3])), e16);

        if (tid < TT) bp[t * TT + jj] = (unsigned char)bi;
    }

    __syncwarp();   // bp + final score vector visible

    float* o = out_tags + (size_t)b * SS;

    // cooperative zero of the masked tail [nw, SS)
    for (int t = nw + tid; t < SS; t += 32) o[t] = 0.0f;

    if (tid == 0) {
        const float* s = sc[nw & 1];
        int cur = 0;
        float bv = s[0] + end_trans[0];
#pragma unroll
        for (int i = 1; i < TT; i++) {
            float v = s[i] + end_trans[i];
            if (v > bv) { bv = v; cur = i; }
        }
        for (int t = nw - 1; t >= 1; t--) {
            o[t] = (float)cur;
            cur = bp[t * TT + cur];
        }
        o[0] = (float)cur;   // nwords >= 1
    }
}

// ---------------------------------------------------------------------------
// Inputs: x, W, b, transitions, start_trans, end_trans, nwords
// Output: [padded_tags (B*S) | feats (B*S*T)] float32
// ---------------------------------------------------------------------------
extern "C" void kernel_launch(void* const* d_in, const int* in_sizes, int n_in,
                              void* d_out, int out_size)
{
    const float* x     = (const float*)d_in[0];
    const float* W     = (const float*)d_in[1];
    const float* bias  = (const float*)d_in[2];
    const float* trans = (const float*)d_in[3];
    const float* st    = (const float*)d_in[4];
    const float* en    = (const float*)d_in[5];
    const int*   nw    = (const int*)d_in[6];

    float* out   = (float*)d_out;
    float* tags  = out;                // B*S
    float* feats = out + BB * SS;      // B*S*T

    gemm_feats<<<(BB * SS) / ROWS_PB, GEMM_THREADS>>>(x, W, bias, feats);
    viterbi_kernel<<<BB, 128>>>(feats, trans, st, en, nw, tags);
}

// round 12
// speedup vs baseline: 1.3053x; 1.0635x over previous
#include <cuda_runtime.h>
#include <cuda_bf16.h>

#define BB 64
#define SS 512
#define HH 1024
#define TT 17

typedef unsigned long long u64;

__device__ __forceinline__ u64 fma2(u64 a, u64 b, u64 c) {
    u64 d;
    asm("fma.rn.f32x2 %0, %1, %2, %3;" : "=l"(d) : "l"(a), "l"(b), "l"(c));
    return d;
}
__device__ __forceinline__ u64 add2(u64 a, u64 b) {
    u64 d;
    asm("add.rn.f32x2 %0, %1, %2;" : "=l"(d) : "l"(a), "l"(b));
    return d;
}
__device__ __forceinline__ u64 pack2(float lo, float hi) {
    u64 d;
    asm("mov.b64 %0, {%1, %2};" : "=l"(d) : "f"(lo), "f"(hi));
    return d;
}

// ---------------------------------------------------------------------------
// GEMM: feats[r][t] = sum_h x[r][h]*W[t][h] + b[t]  (M=32768, K=1024, N=17)
// 128 threads / 64 rows per block, tags split 2-way (g=0: tags 0..8,
// g=1: tags 9..16). DOUBLE-BUFFERED smem staging: LDG tile kt+1 into
// registers while computing tile kt, then STS to the other buffer =>
// DRAM latency off the per-tile critical path. 44.1 KB static smem.
// ---------------------------------------------------------------------------
#define GEMM_THREADS 128
#define ROWS_PB      64
#define KTILE        64
#define NKT          (HH / KTILE)
#define XS_STRIDE    68
#define WT_STRIDE    68

template<int T0, int CNT>
__device__ __forceinline__ void acc_tile(const float* __restrict__ xs_row,
                                         const float* __restrict__ wt, u64* acc)
{
#pragma unroll
    for (int c = 0; c < 16; c++) {
        ulonglong2 xv = *(const ulonglong2*)(xs_row + c * 4);
#pragma unroll
        for (int u = 0; u < CNT; u++) {
            ulonglong2 wv = *(const ulonglong2*)(wt + (T0 + u) * WT_STRIDE + c * 4);
            acc[u] = fma2(xv.x, wv.x, acc[u]);
            acc[u] = fma2(xv.y, wv.y, acc[u]);
        }
    }
}

__global__ __launch_bounds__(GEMM_THREADS) void gemm_feats(
    const float* __restrict__ x, const float* __restrict__ W,
    const float* __restrict__ bias, float* __restrict__ feats)
{
    __shared__ float xs[2][ROWS_PB * XS_STRIDE];   // 2 x 17408 B
    __shared__ float wt[2][TT * WT_STRIDE];        // 2 x  4624 B

    const int tid  = threadIdx.x;
    const int r    = tid & 63;         // row within tile
    const int g    = tid >> 6;         // tag group
    const int row0 = blockIdx.x * ROWS_PB;

    // staging coordinates (fixed per thread)
    const int s_rr0 = (tid) >> 4,            s_cc0 = (tid) & 15;
    const int s_rr1 = (tid + 128) >> 4,      s_cc1 = (tid + 128) & 15;
    // generic via loop below

    float4 px[8];
    float4 pw[3];

    // ---- prefetch tile 0 ----
#pragma unroll
    for (int p = 0; p < 8; p++) {
        int idx = tid + p * GEMM_THREADS;
        int rr = idx >> 4, cc = idx & 15;
        px[p] = *(const float4*)(x + (size_t)(row0 + rr) * HH + cc * 4);
    }
#pragma unroll
    for (int p = 0; p < 3; p++) {
        int idx = tid + p * GEMM_THREADS;
        if (idx < TT * 16) {
            int t = idx >> 4, cc = idx & 15;
            pw[p] = *(const float4*)(W + (size_t)t * HH + cc * 4);
        }
    }

    u64 acc[9];
#pragma unroll
    for (int u = 0; u < 9; u++) acc[u] = 0ull;

    // ---- store tile 0 into buffer 0 ----
#pragma unroll
    for (int p = 0; p < 8; p++) {
        int idx = tid + p * GEMM_THREADS;
        int rr = idx >> 4, cc = idx & 15;
        *(float4*)&xs[0][rr * XS_STRIDE + cc * 4] = px[p];
    }
#pragma unroll
    for (int p = 0; p < 3; p++) {
        int idx = tid + p * GEMM_THREADS;
        if (idx < TT * 16) {
            int t = idx >> 4, cc = idx & 15;
            *(float4*)&wt[0][t * WT_STRIDE + cc * 4] = pw[p];
        }
    }
    __syncthreads();

    for (int kt = 0; kt < NKT; kt++) {
        const int cur = kt & 1;

        // prefetch tile kt+1 into registers (overlaps with compute below)
        if (kt + 1 < NKT) {
            const float* xk = x + (kt + 1) * KTILE;
#pragma unroll
            for (int p = 0; p < 8; p++) {
                int idx = tid + p * GEMM_THREADS;
                int rr = idx >> 4, cc = idx & 15;
                px[p] = *(const float4*)(xk + (size_t)(row0 + rr) * HH + cc * 4);
            }
            const float* wk = W + (kt + 1) * KTILE;
#pragma unroll
            for (int p = 0; p < 3; p++) {
                int idx = tid + p * GEMM_THREADS;
                if (idx < TT * 16) {
                    int t = idx >> 4, cc = idx & 15;
                    pw[p] = *(const float4*)(wk + (size_t)t * HH + cc * 4);
                }
            }
        }

        // compute tile kt from buffer cur
        const float* xs_row = &xs[cur][r * XS_STRIDE];
        if (g == 0) acc_tile<0, 9>(xs_row, wt[cur], acc);
        else        acc_tile<9, 8>(xs_row, wt[cur], acc);

        // stage tile kt+1 into the other buffer, then barrier
        if (kt + 1 < NKT) {
            const int nxt = cur ^ 1;
#pragma unroll
            for (int p = 0; p < 8; p++) {
                int idx = tid + p * GEMM_THREADS;
                int rr = idx >> 4, cc = idx & 15;
                *(float4*)&xs[nxt][rr * XS_STRIDE + cc * 4] = px[p];
            }
#pragma unroll
            for (int p = 0; p < 3; p++) {
                int idx = tid + p * GEMM_THREADS;
                if (idx < TT * 16) {
                    int t = idx >> 4, cc = idx & 15;
                    *(float4*)&wt[nxt][t * WT_STRIDE + cc * 4] = pw[p];
                }
            }
            __syncthreads();
        }
    }

    float* o = feats + (size_t)(row0 + r) * TT;
    if (g == 0) {
#pragma unroll
        for (int u = 0; u < 9; u++) {
            float2 p = *(float2*)&acc[u];
            o[u] = p.x + p.y + bias[u];
        }
    } else {
#pragma unroll
        for (int u = 0; u < 8; u++) {
            float2 p = *(float2*)&acc[u];
            o[9 + u] = p.x + p.y + bias[9 + u];
        }
    }
}

// ---------------------------------------------------------------------------
// Viterbi: unchanged from R11 (69.1 us). One block per batch; 4 warps fill
// feats smem; warp 0 runs the scan with smem score exchange, packed f32x2
// candidate adds, FMNMX max tree, parallel-equality + IMNMX argmax.
// ---------------------------------------------------------------------------
__global__ __launch_bounds__(128) void viterbi_kernel(
    const float* __restrict__ feats, const float* __restrict__ trans,
    const float* __restrict__ start_trans, const float* __restrict__ end_trans,
    const int* __restrict__ nwords, float* __restrict__ out_tags)
{
    __shared__ float fs[SS * TT];                  // 34816 B
    __shared__ unsigned char bp[SS * TT];          //  8704 B
    __shared__ __align__(16) float sc[2][20];      // double-buffered score vec

    const int b   = blockIdx.x;
    const int tid = threadIdx.x;
    const int nw  = nwords[b];

    const float4* fb4 = (const float4*)(feats + (size_t)b * SS * TT);
    const int n4 = (nw * TT + 3) >> 2;
    for (int i = tid; i < n4; i += 128)
        ((float4*)fs)[i] = fb4[i];
    __syncthreads();

    if (tid >= 32) return;

    const int jj = (tid < TT) ? tid : (TT - 1);

    float tcol[TT];
#pragma unroll
    for (int i = 0; i < TT; i++) tcol[i] = trans[i * TT + jj];
    u64 tc2[8];
#pragma unroll
    for (int p = 0; p < 8; p++) tc2[p] = pack2(tcol[2 * p], tcol[2 * p + 1]);
    const float tc16 = tcol[16];

    float score = start_trans[jj] + fs[jj];
    if (tid < TT) sc[1][jj] = score;
    __syncwarp();

    for (int t = 1; t < nw; t++) {
        const float* s = sc[t & 1];
        const float f  = fs[t * TT + jj];

        ulonglong2 sA = *(const ulonglong2*)(s);
        ulonglong2 sB = *(const ulonglong2*)(s + 4);
        ulonglong2 sC = *(const ulonglong2*)(s + 8);
        ulonglong2 sD = *(const ulonglong2*)(s + 12);
        float s16 = s[16];

        u64 c2[8];
        c2[0] = add2(sA.x, tc2[0]); c2[1] = add2(sA.y, tc2[1]);
        c2[2] = add2(sB.x, tc2[2]); c2[3] = add2(sB.y, tc2[3]);
        c2[4] = add2(sC.x, tc2[4]); c2[5] = add2(sC.y, tc2[5]);
        c2[6] = add2(sD.x, tc2[6]); c2[7] = add2(sD.y, tc2[7]);
        float c16 = s16 + tc16;

        float c[16];
#pragma unroll
        for (int p = 0; p < 8; p++) {
            float2 cp = *(float2*)&c2[p];
            c[2 * p] = cp.x; c[2 * p + 1] = cp.y;
        }

        float m8[8];
#pragma unroll
        for (int p = 0; p < 8; p++) m8[p] = fmaxf(c[2 * p], c[2 * p + 1]);
        float m4[4];
#pragma unroll
        for (int p = 0; p < 4; p++) m4[p] = fmaxf(m8[2 * p], m8[2 * p + 1]);
        float bv = fmaxf(fmaxf(fmaxf(m4[0], m4[1]), fmaxf(m4[2], m4[3])), c16);

        score = bv + f;
        if (tid < TT) sc[(t + 1) & 1][jj] = score;
        __syncwarp();

        int e[16];
#pragma unroll
        for (int i = 0; i < 16; i++) e[i] = (c[i] == bv) ? i : 31;
        int e16 = (c16 == bv) ? 16 : 31;
        int i8[8];
#pragma unroll
        for (int p = 0; p < 8; p++) i8[p] = min(e[2 * p], e[2 * p + 1]);
        int i4[4];
#pragma unroll
        for (int p = 0; p < 4; p++) i4[p] = min(i8[2 * p], i8[2 * p + 1]);
        int bi = min(min(min(i4[0], i4[1]), min(i4[2], i4[3])), e16);

        if (tid < TT) bp[t * TT + jj] = (unsigned char)bi;
    }

    __syncwarp();

    float* o = out_tags + (size_t)b * SS;
    for (int t = nw + tid; t < SS; t += 32) o[t] = 0.0f;

    if (tid == 0) {
        const float* s = sc[nw & 1];
        int cur = 0;
        float bv = s[0] + end_trans[0];
#pragma unroll
        for (int i = 1; i < TT; i++) {
            float v = s[i] + end_trans[i];
            if (v > bv) { bv = v; cur = i; }
        }
        for (int t = nw - 1; t >= 1; t--) {
            o[t] = (float)cur;
            cur = bp[t * TT + cur];
        }
        o[0] = (float)cur;
    }
}

// ---------------------------------------------------------------------------
// Inputs: x, W, b, transitions, start_trans, end_trans, nwords
// Output: [padded_tags (B*S) | feats (B*S*T)] float32
// ---------------------------------------------------------------------------
extern "C" void kernel_launch(void* const* d_in, const int* in_sizes, int n_in,
                              void* d_out, int out_size)
{
    const float* x     = (const float*)d_in[0];
    const float* W     = (const float*)d_in[1];
    const float* bias  = (const float*)d_in[2];
    const float* trans = (const float*)d_in[3];
    const float* st    = (const float*)d_in[4];
    const float* en    = (const float*)d_in[5];
    const int*   nw    = (const int*)d_in[6];

    float* out   = (float*)d_out;
    float* tags  = out;                // B*S
    float* feats = out + BB * SS;      // B*S*T

    gemm_feats<<<(BB * SS) / ROWS_PB, GEMM_THREADS>>>(x, W, bias, feats);
    viterbi_kernel<<<BB, 128>>>(feats, trans, st, en, nw, tags);
}

// round 13
// speedup vs baseline: 1.3814x; 1.0583x over previous
#include <cuda_runtime.h>
#include <cuda_bf16.h>

#define BB 64
#define SS 512
#define HH 1024
#define TT 17

typedef unsigned long long u64;

__device__ __forceinline__ u64 fma2(u64 a, u64 b, u64 c) {
    u64 d;
    asm("fma.rn.f32x2 %0, %1, %2, %3;" : "=l"(d) : "l"(a), "l"(b), "l"(c));
    return d;
}
__device__ __forceinline__ u64 add2(u64 a, u64 b) {
    u64 d;
    asm("add.rn.f32x2 %0, %1, %2;" : "=l"(d) : "l"(a), "l"(b));
    return d;
}
__device__ __forceinline__ u64 pack2(float lo, float hi) {
    u64 d;
    asm("mov.b64 %0, {%1, %2};" : "=l"(d) : "f"(lo), "f"(hi));
    return d;
}

// ---------------------------------------------------------------------------
// GEMM: feats[r][t] = sum_h x[r][h]*W[t][h] + b[t]  (M=32768, K=1024, N=17)
// 128 threads / 32 rows per block; tags split 4-way BY WARP (warp0: tags 0-4,
// warp1: 5-8, warp2: 9-12, warp3: 13-16) so W loads stay warp-uniform.
// Grid 1024 => 6.9 blocks/SM => latency actually hidden. Double-buffered
// smem staging (26.7 KB static). Packed fma.rn.f32x2 accumulation.
// ---------------------------------------------------------------------------
#define GEMM_THREADS 128
#define ROWS_PB      32
#define KTILE        64
#define NKT          (HH / KTILE)
#define XS_STRIDE    68
#define WT_STRIDE    68

template<int T0, int CNT>
__device__ __forceinline__ void acc_tile(const float* __restrict__ xs_row,
                                         const float* __restrict__ wt, u64* acc)
{
#pragma unroll
    for (int c = 0; c < 16; c++) {
        ulonglong2 xv = *(const ulonglong2*)(xs_row + c * 4);
#pragma unroll
        for (int u = 0; u < CNT; u++) {
            ulonglong2 wv = *(const ulonglong2*)(wt + (T0 + u) * WT_STRIDE + c * 4);
            acc[u] = fma2(xv.x, wv.x, acc[u]);
            acc[u] = fma2(xv.y, wv.y, acc[u]);
        }
    }
}

__global__ __launch_bounds__(GEMM_THREADS) void gemm_feats(
    const float* __restrict__ x, const float* __restrict__ W,
    const float* __restrict__ bias, float* __restrict__ feats)
{
    __shared__ float xs[2][ROWS_PB * XS_STRIDE];   // 2 x 8704 B
    __shared__ float wt[2][TT * WT_STRIDE];        // 2 x 4624 B

    const int tid  = threadIdx.x;
    const int r    = tid & 31;          // row within tile
    const int g    = tid >> 5;          // warp = tag group
    const int row0 = blockIdx.x * ROWS_PB;

    float4 px[4];
    float4 pw[3];

    // ---- prefetch tile 0 ----
#pragma unroll
    for (int p = 0; p < 4; p++) {
        int idx = tid + p * GEMM_THREADS;
        int rr = idx >> 4, cc = idx & 15;
        px[p] = *(const float4*)(x + (size_t)(row0 + rr) * HH + cc * 4);
    }
#pragma unroll
    for (int p = 0; p < 3; p++) {
        int idx = tid + p * GEMM_THREADS;
        if (idx < TT * 16) {
            int t = idx >> 4, cc = idx & 15;
            pw[p] = *(const float4*)(W + (size_t)t * HH + cc * 4);
        }
    }

    u64 acc[5];
#pragma unroll
    for (int u = 0; u < 5; u++) acc[u] = 0ull;

    // ---- store tile 0 ----
#pragma unroll
    for (int p = 0; p < 4; p++) {
        int idx = tid + p * GEMM_THREADS;
        int rr = idx >> 4, cc = idx & 15;
        *(float4*)&xs[0][rr * XS_STRIDE + cc * 4] = px[p];
    }
#pragma unroll
    for (int p = 0; p < 3; p++) {
        int idx = tid + p * GEMM_THREADS;
        if (idx < TT * 16) {
            int t = idx >> 4, cc = idx & 15;
            *(float4*)&wt[0][t * WT_STRIDE + cc * 4] = pw[p];
        }
    }
    __syncthreads();

    for (int kt = 0; kt < NKT; kt++) {
        const int cur = kt & 1;

        if (kt + 1 < NKT) {   // prefetch next tile into registers
            const float* xk = x + (kt + 1) * KTILE;
#pragma unroll
            for (int p = 0; p < 4; p++) {
                int idx = tid + p * GEMM_THREADS;
                int rr = idx >> 4, cc = idx & 15;
                px[p] = *(const float4*)(xk + (size_t)(row0 + rr) * HH + cc * 4);
            }
            const float* wk = W + (kt + 1) * KTILE;
#pragma unroll
            for (int p = 0; p < 3; p++) {
                int idx = tid + p * GEMM_THREADS;
                if (idx < TT * 16) {
                    int t = idx >> 4, cc = idx & 15;
                    pw[p] = *(const float4*)(wk + (size_t)t * HH + cc * 4);
                }
            }
        }

        const float* xs_row = &xs[cur][r * XS_STRIDE];
        if      (g == 0) acc_tile<0,  5>(xs_row, wt[cur], acc);
        else if (g == 1) acc_tile<5,  4>(xs_row, wt[cur], acc);
        else if (g == 2) acc_tile<9,  4>(xs_row, wt[cur], acc);
        else             acc_tile<13, 4>(xs_row, wt[cur], acc);

        if (kt + 1 < NKT) {
            const int nxt = cur ^ 1;
#pragma unroll
            for (int p = 0; p < 4; p++) {
                int idx = tid + p * GEMM_THREADS;
                int rr = idx >> 4, cc = idx & 15;
                *(float4*)&xs[nxt][rr * XS_STRIDE + cc * 4] = px[p];
            }
#pragma unroll
            for (int p = 0; p < 3; p++) {
                int idx = tid + p * GEMM_THREADS;
                if (idx < TT * 16) {
                    int t = idx >> 4, cc = idx & 15;
                    *(float4*)&wt[nxt][t * WT_STRIDE + cc * 4] = pw[p];
                }
            }
            __syncthreads();
        }
    }

    const int t0  = (g == 0) ? 0 : (g == 1) ? 5 : (g == 2) ? 9 : 13;
    const int cnt = (g == 0) ? 5 : 4;
    float* o = feats + (size_t)(row0 + r) * TT;
#pragma unroll
    for (int u = 0; u < 5; u++) {
        if (u < cnt) {
            float2 p = *(float2*)&acc[u];
            o[t0 + u] = p.x + p.y + bias[t0 + u];
        }
    }
}

// ---------------------------------------------------------------------------
// Viterbi: one block per batch, producer/consumer warp split.
//   warp 0: score recurrence only (smem exchange, packed adds, FMNMX tree),
//           publishes score+bv vectors into a 32-slot ring.
//   warp 1: one 8-step phase behind; recomputes candidates from the ring and
//           does the argmax-index (equality + IMNMX min-tree) + bp stores.
//           Its steps are independent => pipelines, off warp0's chain.
// Sync: named barrier (id 1, 64 threads) once per 8-step phase.
// First-occurrence argmax semantics preserved (equality vs exact bv).
// ---------------------------------------------------------------------------
__global__ __launch_bounds__(128) void viterbi_kernel(
    const float* __restrict__ feats, const float* __restrict__ trans,
    const float* __restrict__ start_trans, const float* __restrict__ end_trans,
    const int* __restrict__ nwords, float* __restrict__ out_tags)
{
    __shared__ float fs[SS * TT];                    // 34816 B
    __shared__ unsigned char bp[SS * TT];            //  8704 B
    __shared__ __align__(16) float sch[32][20];      //  2560 B score ring
    __shared__ __align__(16) float bvh[32][20];      //  2560 B bv ring

    const int b   = blockIdx.x;
    const int tid = threadIdx.x;
    const int nw  = nwords[b];

    // all 128 threads fill feats smem
    const float4* fb4 = (const float4*)(feats + (size_t)b * SS * TT);
    const int n4 = (nw * TT + 3) >> 2;
    for (int i = tid; i < n4; i += 128)
        ((float4*)fs)[i] = fb4[i];
    __syncthreads();

    if (tid >= 64) return;          // warps 2,3 done

    const int wid  = tid >> 5;
    const int lane = tid & 31;
    const int jj   = (lane < TT) ? lane : (TT - 1);

    float tcol[TT];
#pragma unroll
    for (int i = 0; i < TT; i++) tcol[i] = trans[i * TT + jj];
    u64 tc2[8];
#pragma unroll
    for (int p = 0; p < 8; p++) tc2[p] = pack2(tcol[2 * p], tcol[2 * p + 1]);
    const float tc16 = tcol[16];

    // init t = 0 (always unmasked)
    if (wid == 0) {
        float s0 = start_trans[jj] + fs[jj];
        if (lane < TT) sch[0][jj] = s0;
        __syncwarp();
    }

    const int np = (nw - 1 + 7) >> 3;    // number of 8-step phases

    for (int p = 0; p <= np; p++) {
        if (wid == 0 && p < np) {
            // -------- producer: steps of phase p --------
            const int t0 = 1 + p * 8;
            const int t1 = min(t0 + 8, nw);
            for (int t = t0; t < t1; t++) {
                const float f = fs[t * TT + jj];
                const float* s = sch[(t - 1) & 31];
                ulonglong2 sA = *(const ulonglong2*)(s);
                ulonglong2 sB = *(const ulonglong2*)(s + 4);
                ulonglong2 sC = *(const ulonglong2*)(s + 8);
                ulonglong2 sD = *(const ulonglong2*)(s + 12);
                float s16 = s[16];

                u64 c2[8];
                c2[0] = add2(sA.x, tc2[0]); c2[1] = add2(sA.y, tc2[1]);
                c2[2] = add2(sB.x, tc2[2]); c2[3] = add2(sB.y, tc2[3]);
                c2[4] = add2(sC.x, tc2[4]); c2[5] = add2(sC.y, tc2[5]);
                c2[6] = add2(sD.x, tc2[6]); c2[7] = add2(sD.y, tc2[7]);
                float c16 = s16 + tc16;

                float c[16];
#pragma unroll
                for (int q = 0; q < 8; q++) {
                    float2 cp = *(float2*)&c2[q];
                    c[2 * q] = cp.x; c[2 * q + 1] = cp.y;
                }
                float m8[8];
#pragma unroll
                for (int q = 0; q < 8; q++) m8[q] = fmaxf(c[2 * q], c[2 * q + 1]);
                float m4[4];
#pragma unroll
                for (int q = 0; q < 4; q++) m4[q] = fmaxf(m8[2 * q], m8[2 * q + 1]);
                float bv = fmaxf(fmaxf(fmaxf(m4[0], m4[1]), fmaxf(m4[2], m4[3])), c16);

                float sn = bv + f;
                if (lane < TT) {
                    sch[t & 31][jj] = sn;
                    bvh[t & 31][jj] = bv;
                }
                __syncwarp();
            }
        }
        if (wid == 1 && p > 0) {
            // -------- consumer: argmax-index for phase p-1 --------
            const int t0 = 1 + (p - 1) * 8;
            const int t1 = min(t0 + 8, nw);
            for (int t = t0; t < t1; t++) {
                const float* s = sch[(t - 1) & 31];
                ulonglong2 sA = *(const ulonglong2*)(s);
                ulonglong2 sB = *(const ulonglong2*)(s + 4);
                ulonglong2 sC = *(const ulonglong2*)(s + 8);
                ulonglong2 sD = *(const ulonglong2*)(s + 12);
                float s16 = s[16];
                float bv  = bvh[t & 31][jj];

                u64 c2[8];
                c2[0] = add2(sA.x, tc2[0]); c2[1] = add2(sA.y, tc2[1]);
                c2[2] = add2(sB.x, tc2[2]); c2[3] = add2(sB.y, tc2[3]);
                c2[4] = add2(sC.x, tc2[4]); c2[5] = add2(sC.y, tc2[5]);
                c2[6] = add2(sD.x, tc2[6]); c2[7] = add2(sD.y, tc2[7]);
                float c16 = s16 + tc16;

                float c[16];
#pragma unroll
                for (int q = 0; q < 8; q++) {
                    float2 cp = *(float2*)&c2[q];
                    c[2 * q] = cp.x; c[2 * q + 1] = cp.y;
                }
                int e[16];
#pragma unroll
                for (int i = 0; i < 16; i++) e[i] = (c[i] == bv) ? i : 31;
                int e16 = (c16 == bv) ? 16 : 31;
                int i8[8];
#pragma unroll
                for (int q = 0; q < 8; q++) i8[q] = min(e[2 * q], e[2 * q + 1]);
                int i4[4];
#pragma unroll
                for (int q = 0; q < 4; q++) i4[q] = min(i8[2 * q], i8[2 * q + 1]);
                int bi = min(min(min(i4[0], i4[1]), min(i4[2], i4[3])), e16);

                if (lane < TT) bp[t * TT + jj] = (unsigned char)bi;
            }
        }
        asm volatile("bar.sync 1, 64;" ::: "memory");
    }

    // -------- epilogue on warp 0 --------
    if (wid == 0) {
        float* o = out_tags + (size_t)b * SS;
        for (int t = nw + lane; t < SS; t += 32) o[t] = 0.0f;   // masked tail

        if (lane == 0) {
            const float* s = sch[(nw - 1) & 31];
            int cur = 0;
            float bv = s[0] + end_trans[0];
#pragma unroll
            for (int i = 1; i < TT; i++) {
                float v = s[i] + end_trans[i];
                if (v > bv) { bv = v; cur = i; }
            }
            for (int t = nw - 1; t >= 1; t--) {
                o[t] = (float)cur;
                cur = bp[t * TT + cur];
            }
            o[0] = (float)cur;   // nwords >= 1
        }
    }
}

// ---------------------------------------------------------------------------
// Inputs: x, W, b, transitions, start_trans, end_trans, nwords
// Output: [padded_tags (B*S) | feats (B*S*T)] float32
// ---------------------------------------------------------------------------
extern "C" void kernel_launch(void* const* d_in, const int* in_sizes, int n_in,
                              void* d_out, int out_size)
{
    const float* x     = (const float*)d_in[0];
    const float* W     = (const float*)d_in[1];
    const float* bias  = (const float*)d_in[2];
    const float* trans = (const float*)d_in[3];
    const float* st    = (const float*)d_in[4];
    const float* en    = (const float*)d_in[5];
    const int*   nw    = (const int*)d_in[6];

    float* out   = (float*)d_out;
    float* tags  = out;                // B*S
    float* feats = out + BB * SS;      // B*S*T

    gemm_feats<<<(BB * SS) / ROWS_PB, GEMM_THREADS>>>(x, W, bias, feats);
    viterbi_kernel<<<BB, 128>>>(feats, trans, st, en, nw, tags);
}